// round 1
// baseline (speedup 1.0000x reference)
#include <cuda_runtime.h>
#include <math.h>

// ---------------------------------------------------------------------------
// Style2ResidualBlock1DSrc: modulated conv1d, restructured as
//   s[b,i]      = style_b[i] + LIN_SCALE * (concat(c_src,c_trg)[b] . style_w[i])
//   demod[b,o]  = rsqrt(CONV_SCALE^2 * sum_i (sum_k weight[o,i,k]^2) s[b,i]^2 + 1e-8)
//   out[b,o,t]  = CONV_SCALE*demod[b,o] * sum_{i,k} weight[o,i,k]*s[b,i]*x[b,i,t+k-1]
// Heavy op = 16 batched implicit-im2col GEMMs done with packed f32x2 FMA.
// ---------------------------------------------------------------------------

#define B_      16
#define CIN     512
#define COUT    512
#define T_      2048
#define KW      3

#define LIN_SCALE  0.0625f                    // 1/sqrt(256)
#define CONV_SCALE 1.4731391274719738e-2f     // 1/sqrt(512*9)
#define CONV_SCALE2 (1.0f/4608.0f)

// Scratch (device globals: allocation-free rule)
__device__ float g_s[B_ * CIN];           // style codes
__device__ float g_demod[B_ * COUT];      // demod factors
__device__ float g_wt[CIN * KW * COUT];   // weight transposed to [i][k][o]

// ---- packed f32x2 helpers (FFMA2 only reachable via inline PTX) ----
#define FMA2(d, a, b, c) \
    asm("fma.rn.f32x2 %0, %1, %2, %3;" : "=l"(d) : "l"(a), "l"(b), "l"(c))
#define PACK_DUP(d, f) \
    asm("mov.b64 %0, {%1, %1};" : "=l"(d) : "f"(f))
#define UNPACK2(lo, hi, v) \
    asm("mov.b64 {%0, %1}, %2;" : "=f"(lo), "=f"(hi) : "l"(v))

// ---------------------------------------------------------------------------
// Kernel 1: style codes s[b,i]
// ---------------------------------------------------------------------------
__global__ void style_kernel(const float* __restrict__ c_src,
                             const float* __restrict__ c_trg,
                             const float* __restrict__ style_w,
                             const float* __restrict__ style_b)
{
    int b = blockIdx.x;
    int i = threadIdx.x;            // 512 threads
    __shared__ float c[256];
    if (i < 128)       c[i] = c_src[b * 128 + i];
    else if (i < 256)  c[i] = c_trg[b * 128 + (i - 128)];
    __syncthreads();

    const float* row = style_w + (size_t)i * 256;
    float acc = 0.f;
#pragma unroll 8
    for (int j = 0; j < 256; j++) acc += row[j] * c[j];
    g_s[b * CIN + i] = style_b[i] + LIN_SCALE * acc;
}

// ---------------------------------------------------------------------------
// Kernel 2: transpose weight [o][i][k] -> g_wt[(i*3+k)*512 + o]
// ---------------------------------------------------------------------------
__global__ void trans_kernel(const float* __restrict__ weight)
{
    int idx = blockIdx.x * 256 + threadIdx.x;   // 786432 total
    if (idx >= CIN * KW * COUT) return;
    int o   = idx & (COUT - 1);
    int ik  = idx >> 9;          // 0..1535
    int k   = ik % 3;
    int i   = ik / 3;
    g_wt[idx] = weight[(size_t)o * (CIN * KW) + i * KW + k];
}

// ---------------------------------------------------------------------------
// Kernel 3: demod[b,o]
// One block (256 thr) per o; accumulates over i for all 16 b at once.
// ---------------------------------------------------------------------------
__global__ void demod_kernel(const float* __restrict__ weight)
{
    int o   = blockIdx.x;
    int tid = threadIdx.x;

    float acc[B_];
#pragma unroll
    for (int b = 0; b < B_; b++) acc[b] = 0.f;

    for (int i = tid; i < CIN; i += 256) {
        const float* wp = weight + (size_t)o * (CIN * KW) + i * KW;
        float w0 = wp[0], w1 = wp[1], w2 = wp[2];
        float wsq = w0 * w0 + w1 * w1 + w2 * w2;
#pragma unroll
        for (int b = 0; b < B_; b++) {
            float sv = g_s[b * CIN + i];
            acc[b] += wsq * sv * sv;
        }
    }
    // warp reduce
#pragma unroll
    for (int b = 0; b < B_; b++)
#pragma unroll
        for (int off = 16; off; off >>= 1)
            acc[b] += __shfl_down_sync(0xffffffffu, acc[b], off);

    __shared__ float red[8][B_];
    int lane = tid & 31, warp = tid >> 5;
    if (lane == 0)
#pragma unroll
        for (int b = 0; b < B_; b++) red[warp][b] = acc[b];
    __syncthreads();

    if (tid < B_) {
        float t = 0.f;
#pragma unroll
        for (int w = 0; w < 8; w++) t += red[w][tid];
        g_demod[tid * COUT + o] = rsqrtf(CONV_SCALE2 * t + 1e-8f);
    }
}

// ---------------------------------------------------------------------------
// Kernel 4: main conv. 128(o) x 128(t) tile per CTA, 8x8 per thread held as
// 4 o-pairs x 8 t in packed f32x2 accumulators. I-chunk = 16.
// ---------------------------------------------------------------------------
#define I_BLK 16
#define O_BLK 128
#define T_BLK 128
#define XROW  132   // 130 used, padded to keep 16B alignment

__global__ __launch_bounds__(256, 2)
void conv_kernel(const float* __restrict__ x, float* __restrict__ out)
{
    __shared__ float Xs[I_BLK][XROW];
    __shared__ float Ws[I_BLK][KW][O_BLK];

    int b  = blockIdx.z;
    int o0 = blockIdx.y * O_BLK;
    int t0 = blockIdx.x * T_BLK;
    int tid = threadIdx.x;
    int tx = tid & 15;   // t micro-tile
    int ty = tid >> 4;   // o micro-tile

    const float* xb = x + (size_t)b * CIN * T_;

    unsigned long long acc[4][8];
#pragma unroll
    for (int p = 0; p < 4; p++)
#pragma unroll
        for (int tt = 0; tt < 8; tt++) acc[p][tt] = 0ull;

    for (int i0 = 0; i0 < CIN; i0 += I_BLK) {
        // --- load modulated x tile: 16 x 130 (t0-1 .. t0+128) ---
        for (int idx = tid; idx < I_BLK * 130; idx += 256) {
            int i  = idx / 130;
            int tt = idx - i * 130;
            int tg = t0 + tt - 1;
            float v = 0.f;
            if (tg >= 0 && tg < T_) {
                float sv = g_s[b * CIN + i0 + i];
                v = xb[(size_t)(i0 + i) * T_ + tg] * sv;
            }
            Xs[i][tt] = v;
        }
        // --- load weight tile: [i][k][o], o contiguous (coalesced from g_wt) ---
        for (int idx = tid; idx < I_BLK * KW * O_BLK; idx += 256) {
            int o    = idx & (O_BLK - 1);
            int rest = idx >> 7;
            int k    = rest % 3;
            int i    = rest / 3;
            Ws[i][k][o] = g_wt[(size_t)((i0 + i) * KW + k) * COUT + o0 + o];
        }
        __syncthreads();

#pragma unroll 4
        for (int i = 0; i < I_BLK; i++) {
            float xr[10];
            float4 xa = *(const float4*)&Xs[i][tx * 8];
            float4 xb4 = *(const float4*)&Xs[i][tx * 8 + 4];
            xr[0] = xa.x; xr[1] = xa.y; xr[2] = xa.z; xr[3] = xa.w;
            xr[4] = xb4.x; xr[5] = xb4.y; xr[6] = xb4.z; xr[7] = xb4.w;
            xr[8] = Xs[i][tx * 8 + 8];
            xr[9] = Xs[i][tx * 8 + 9];

            unsigned long long xd[10];
#pragma unroll
            for (int d = 0; d < 10; d++) PACK_DUP(xd[d], xr[d]);

#pragma unroll
            for (int k = 0; k < KW; k++) {
                unsigned long long wv[4];
#pragma unroll
                for (int p = 0; p < 4; p++)
                    wv[p] = *(const unsigned long long*)&Ws[i][k][ty * 8 + 2 * p];
#pragma unroll
                for (int p = 0; p < 4; p++)
#pragma unroll
                    for (int tt = 0; tt < 8; tt++)
                        FMA2(acc[p][tt], wv[p], xd[tt + k], acc[p][tt]);
            }
        }
        __syncthreads();
    }

    // --- epilogue: scale by CONV_SCALE*demod and store ---
#pragma unroll
    for (int p = 0; p < 4; p++) {
        float r0[8], r1[8];
#pragma unroll
        for (int tt = 0; tt < 8; tt++) UNPACK2(r0[tt], r1[tt], acc[p][tt]);

        int orow = o0 + ty * 8 + 2 * p;
        float s0 = CONV_SCALE * g_demod[b * COUT + orow];
        float s1 = CONV_SCALE * g_demod[b * COUT + orow + 1];

        float* p0 = out + ((size_t)(b * COUT + orow)) * T_ + t0 + tx * 8;
        float* p1 = p0 + T_;

        float4 a0 = make_float4(r0[0]*s0, r0[1]*s0, r0[2]*s0, r0[3]*s0);
        float4 a1 = make_float4(r0[4]*s0, r0[5]*s0, r0[6]*s0, r0[7]*s0);
        float4 b0 = make_float4(r1[0]*s1, r1[1]*s1, r1[2]*s1, r1[3]*s1);
        float4 b1 = make_float4(r1[4]*s1, r1[5]*s1, r1[6]*s1, r1[7]*s1);
        *(float4*)p0       = a0;
        *(float4*)(p0 + 4) = a1;
        *(float4*)p1       = b0;
        *(float4*)(p1 + 4) = b1;
    }
}

// ---------------------------------------------------------------------------
extern "C" void kernel_launch(void* const* d_in, const int* in_sizes, int n_in,
                              void* d_out, int out_size)
{
    const float* x       = (const float*)d_in[0];
    const float* c_src   = (const float*)d_in[1];
    const float* c_trg   = (const float*)d_in[2];
    const float* style_w = (const float*)d_in[3];
    const float* style_b = (const float*)d_in[4];
    const float* weight  = (const float*)d_in[5];
    float* out = (float*)d_out;

    style_kernel<<<B_, 512>>>(c_src, c_trg, style_w, style_b);
    trans_kernel<<<(CIN * KW * COUT + 255) / 256, 256>>>(weight);
    demod_kernel<<<COUT, 256>>>(weight);
    conv_kernel<<<dim3(T_ / T_BLK, COUT / O_BLK, B_), 256>>>(x, out);
}